// round 15
// baseline (speedup 1.0000x reference)
#include <cuda_runtime.h>
#include <cuda_bf16.h>
#include <cuda_fp16.h>
#include <stdint.h>

#define BB 8
#define TT 2048
#define CC 512
#define HH 64
#define SCALEF 0.044194173824159216f   // 512^-0.5
#define C2F    0.063762484904288f      // SCALEF * log2(e)

// ---------------- scratch (device globals: allocation-free) ----------------
__device__ __half g_qhi[BB*TT*HH];                    // fp16 (1-term S)
__device__ __half g_khi[BB*TT*HH];                    // fp16, hi only
__device__ __half g_vhi[BB*TT*HH];                    // fp16, hi only
__device__ __nv_bfloat16 g_wthi[3*HH*CC], g_wtlo[3*HH*CC];   // [w][h][c]
__device__ float g_lpar[8*BB*TT];

// ---------------- helpers ----------------
__device__ __forceinline__ uint32_t su(const void* p) {
  uint32_t a;
  asm("{ .reg .u64 t; cvta.to.shared.u64 t, %1; cvt.u32.u64 %0, t; }" : "=r"(a) : "l"(p));
  return a;
}
__device__ __forceinline__ void ldsm4(uint32_t* r, uint32_t a) {
  asm volatile("ldmatrix.sync.aligned.m8n8.x4.shared.b16 {%0,%1,%2,%3}, [%4];"
    : "=r"(r[0]), "=r"(r[1]), "=r"(r[2]), "=r"(r[3]) : "r"(a));
}
__device__ __forceinline__ void ldsm4t(uint32_t* r, uint32_t a) {
  asm volatile("ldmatrix.sync.aligned.m8n8.x4.trans.shared.b16 {%0,%1,%2,%3}, [%4];"
    : "=r"(r[0]), "=r"(r[1]), "=r"(r[2]), "=r"(r[3]) : "r"(a));
}
__device__ __forceinline__ void mma16816(float* d, const uint32_t* a, uint32_t b0, uint32_t b1) {
  asm volatile("mma.sync.aligned.m16n8k16.row.col.f32.bf16.bf16.f32 "
    "{%0,%1,%2,%3}, {%4,%5,%6,%7}, {%8,%9}, {%0,%1,%2,%3};"
    : "+f"(d[0]), "+f"(d[1]), "+f"(d[2]), "+f"(d[3])
    : "r"(a[0]), "r"(a[1]), "r"(a[2]), "r"(a[3]), "r"(b0), "r"(b1));
}
__device__ __forceinline__ void mma16816h(float* d, const uint32_t* a, uint32_t b0, uint32_t b1) {
  asm volatile("mma.sync.aligned.m16n8k16.row.col.f32.f16.f16.f32 "
    "{%0,%1,%2,%3}, {%4,%5,%6,%7}, {%8,%9}, {%0,%1,%2,%3};"
    : "+f"(d[0]), "+f"(d[1]), "+f"(d[2]), "+f"(d[3])
    : "r"(a[0]), "r"(a[1]), "r"(a[2]), "r"(a[3]), "r"(b0), "r"(b1));
}
__device__ __forceinline__ void split_pack(float a, float b, uint32_t& hi, uint32_t& lo) {
  __nv_bfloat162 h = __floats2bfloat162_rn(a, b);
  __nv_bfloat162 l = __floats2bfloat162_rn(a - __bfloat162float(h.x),
                                           b - __bfloat162float(h.y));
  hi = *reinterpret_cast<uint32_t*>(&h);
  lo = *reinterpret_cast<uint32_t*>(&l);
}
__device__ __forceinline__ uint32_t packh(float a, float b) {
  __half2 h = __floats2half2_rn(a, b);
  return *reinterpret_cast<uint32_t*>(&h);
}
__device__ __forceinline__ void cpa16(uint32_t s, const void* g) {
  asm volatile("cp.async.cg.shared.global [%0], [%1], 16;" :: "r"(s), "l"(g) : "memory");
}
__device__ __forceinline__ void stg2cs(float* p, float x, float y) {
  asm volatile("st.global.cs.v2.f32 [%0], {%1, %2};" :: "l"(p), "f"(x), "f"(y) : "memory");
}
#define CP_COMMIT() asm volatile("cp.async.commit_group;" ::: "memory")
#define CP_WAIT0()  asm volatile("cp.async.wait_group 0;" ::: "memory")

// ---------------- K0: weight transpose + split ----------------
__global__ void k0(const float* __restrict__ Wq, const float* __restrict__ Wk,
                   const float* __restrict__ Wv) {
  int idx = blockIdx.x * 256 + threadIdx.x;          // < 3*64*512
  int w = idx >> 15, rem = idx & 32767, h = rem >> 9, c = rem & 511;
  const float* W = (w == 0) ? Wq : ((w == 1) ? Wk : Wv);
  float v = W[(size_t)c * HH + h];
  __nv_bfloat16 hi = __float2bfloat16(v);
  g_wthi[idx] = hi;
  g_wtlo[idx] = __float2bfloat16(v - __bfloat162float(hi));
}

// ---------------- Kz: zero the output head region ----------------
__global__ void kz(float* __restrict__ out) {
  ((float4*)out)[blockIdx.x * 256 + threadIdx.x] = make_float4(0, 0, 0, 0);
}

// ---------------- K1: QKV on HMMA, split by output. grid=(128,3) ------------
// blockIdx.y = o (0:Q 1:K 2:V). smem: XH@0 XL@18432 | WH@36864 WL@46080 (55296)
__global__ __launch_bounds__(256, 3) void qkv(const float* __restrict__ x) {
  extern __shared__ char S[];
  const uint32_t XH = 0, XL = 18432, WH = 36864, WL = 46080;
  const int t = threadIdx.x, w = t >> 5, lane = t & 31;
  const int g = lane >> 2, tq = lane & 3;
  const int row0 = blockIdx.x * 128;
  const int o = blockIdx.y;
  const uint32_t sb = su(S);
  const uint32_t arow = 16 * w + (lane & 15), aoff8 = (lane >> 4) * 8;
  const uint32_t brow = (lane & 7) + ((lane >> 4) & 1) * 8;
  const uint32_t boff8 = ((lane >> 3) & 1) * 8;

  float acc[8][4] = {};

  for (int kci = 0; kci < 8; kci++) {
    __syncthreads();
#pragma unroll
    for (int e = 0; e < 16; e++) {
      int idx = t + e * 256, r = idx >> 5, cp = idx & 31;
      float2 xv = *(const float2*)(x + (size_t)(row0 + r) * CC + kci * 64 + cp * 2);
      uint32_t hi, lo; split_pack(xv.x, xv.y, hi, lo);
      uint32_t off = (uint32_t)(r * 144 + cp * 4);
      *(uint32_t*)(S + XH + off) = hi;
      *(uint32_t*)(S + XL + off) = lo;
    }
#pragma unroll
    for (int e = 0; e < 8; e++) {
      int idx = t + e * 256;                 // < 2048
      int h = idx >> 5, cp = idx & 31;
      uint32_t gi = (uint32_t)(o * 16384 + h * 256 + kci * 32 + cp);
      uint32_t off = WH + h * 144 + cp * 4;
      *(uint32_t*)(S + off)        = ((const uint32_t*)g_wthi)[gi];
      *(uint32_t*)(S + off + 9216) = ((const uint32_t*)g_wtlo)[gi];
    }
    __syncthreads();

#pragma unroll
    for (int s = 0; s < 4; s++) {
      uint32_t ah[4], al[4];
      uint32_t qa = sb + XH + arow * 144 + (s * 16 + aoff8) * 2;
      ldsm4(ah, qa);
      ldsm4(al, qa + XL);
#pragma unroll
      for (int p = 0; p < 4; p++) {
        uint32_t bh[4], bl[4];
        uint32_t ka = sb + WH + (p * 16 + brow) * 144 + (s * 16 + boff8) * 2;
        ldsm4(bh, ka);
        ldsm4(bl, ka + 9216);
        mma16816(acc[2*p],   ah, bh[0], bh[1]);
        mma16816(acc[2*p],   al, bh[0], bh[1]);
        mma16816(acc[2*p],   ah, bl[0], bl[1]);
        mma16816(acc[2*p+1], ah, bh[2], bh[3]);
        mma16816(acc[2*p+1], al, bh[2], bh[3]);
        mma16816(acc[2*p+1], ah, bl[2], bl[3]);
      }
    }
  }

  const size_t ra = (size_t)(row0 + 16 * w + g), rb = ra + 8;
  uint32_t* d = (uint32_t*)(o == 0 ? g_qhi : (o == 1 ? g_khi : g_vhi));
#pragma unroll
  for (int nf = 0; nf < 8; nf++) {
    d[ra * 32 + nf * 4 + tq] = packh(acc[nf][0], acc[nf][1]);
    d[rb * 32 + nf * 4 + tq] = packh(acc[nf][2], acc[nf][3]);
  }
}

// ---------------- K2a: row-sum pass. grid=(8,128), block=256 ----------------
// Q hoisted to registers; K double-buffer reuses the Q smem region.
// smem: 18432 B total (Q staging, then K buf0@0 / buf1@9216)
__global__ __launch_bounds__(256, 3) void attnA() {
  extern __shared__ char S[];
  const uint32_t KSZ = 9216;
  const int t = threadIdx.x, w = t >> 5, lane = t & 31;
  const int g = lane >> 2, tq = lane & 3;
  const int b = blockIdx.x;
  const int rt = 15 - ((int)blockIdx.y >> 3), chunk = blockIdx.y & 7;
  const int jt0 = chunk * 4;
  const int ntiles = min(4, 2 * rt + 2 - jt0);
  const int i0 = rt * 128;
  const uint32_t sb = su(S);

  float la0 = 0.0f, la1 = 0.0f, lb0 = 0.0f, lb1 = 0.0f;
  const int ia = i0 + 16 * w + g, ib = ia + 8;

  if (ntiles > 0) {
    // stage Q through smem, hoist fragments to registers
#pragma unroll
    for (int e = 0; e < 4; e++) {
      int idx = t + e * 256, r = idx >> 3, c8 = idx & 7;   // idx < 1024
      size_t gb = ((size_t)(b * TT + i0 + r) * 64 + c8 * 8) * 2;
      cpa16(sb + (uint32_t)(r * 144 + c8 * 16), (const char*)g_qhi + gb);
    }
    CP_COMMIT(); CP_WAIT0();
    __syncthreads();
    const uint32_t arow = 16 * w + (lane & 15), aoff8 = (lane >> 4) * 8;
    uint32_t qa[4][4];
#pragma unroll
    for (int s = 0; s < 4; s++)
      ldsm4(qa[s], sb + arow * 144 + (s * 16 + aoff8) * 2);
    __syncthreads();   // all warps done with Q smem before K overwrites

    // first K tile -> buf0 (@0)
    {
      const int j0 = jt0 * 64;
#pragma unroll
      for (int e = 0; e < 2; e++) {
        int idx = t + e * 256, r = idx >> 3, c8 = idx & 7;  // idx < 512
        size_t gb = ((size_t)(b * TT + j0 + r) * 64 + c8 * 8) * 2;
        cpa16(sb + (uint32_t)(r * 144 + c8 * 16), (const char*)g_khi + gb);
      }
    }
    CP_COMMIT();

    const uint32_t brow = (lane & 7) + ((lane >> 4) & 1) * 8;
    const uint32_t boff8 = ((lane >> 3) & 1) * 8;

    for (int ti = 0; ti < ntiles; ti++) {
      const int j0 = (jt0 + ti) * 64;
      CP_WAIT0();
      __syncthreads();

      if (ti + 1 < ntiles) {
        const int jn = (jt0 + ti + 1) * 64;
        const uint32_t nb = ((ti + 1) & 1) * KSZ;
#pragma unroll
        for (int e = 0; e < 2; e++) {
          int idx = t + e * 256, r = idx >> 3, c8 = idx & 7;
          size_t gb = ((size_t)(b * TT + jn + r) * 64 + c8 * 8) * 2;
          cpa16(sb + nb + (uint32_t)(r * 144 + c8 * 16), (const char*)g_khi + gb);
        }
      }
      CP_COMMIT();

      const uint32_t KB = (ti & 1) * KSZ;

      float sa[8][4] = {};
#pragma unroll
      for (int s = 0; s < 4; s++) {
#pragma unroll
        for (int p = 0; p < 4; p++) {
          uint32_t bh[4];
          ldsm4(bh, sb + KB + (p * 16 + brow) * 144 + (s * 16 + boff8) * 2);
          mma16816h(sa[2*p],   qa[s], bh[0], bh[1]);
          mma16816h(sa[2*p+1], qa[s], bh[2], bh[3]);
        }
      }

      if (j0 + 64 <= i0) {
#pragma unroll
        for (int nf = 0; nf < 8; nf++) {
          int j = j0 + nf * 8 + tq * 2;
          float ca0 = (float)(j - ia) * C2F, cb0 = (float)(j - ib) * C2F;
          if (nf & 1) {
            la1 += exp2f(fmaf(sa[nf][0], C2F, ca0));
            la1 += exp2f(fmaf(sa[nf][1], C2F, ca0 + C2F));
            lb1 += exp2f(fmaf(sa[nf][2], C2F, cb0));
            lb1 += exp2f(fmaf(sa[nf][3], C2F, cb0 + C2F));
          } else {
            la0 += exp2f(fmaf(sa[nf][0], C2F, ca0));
            la0 += exp2f(fmaf(sa[nf][1], C2F, ca0 + C2F));
            lb0 += exp2f(fmaf(sa[nf][2], C2F, cb0));
            lb0 += exp2f(fmaf(sa[nf][3], C2F, cb0 + C2F));
          }
        }
      } else {
#pragma unroll
        for (int nf = 0; nf < 8; nf++) {
          int j = j0 + nf * 8 + tq * 2;
          float ca0 = (float)(j - ia) * C2F, cb0 = (float)(j - ib) * C2F;
          if (j     <= ia) la0 += exp2f(fmaf(sa[nf][0], C2F, ca0));
          if (j + 1 <= ia) la1 += exp2f(fmaf(sa[nf][1], C2F, ca0 + C2F));
          if (j     <= ib) lb0 += exp2f(fmaf(sa[nf][2], C2F, cb0));
          if (j + 1 <= ib) lb1 += exp2f(fmaf(sa[nf][3], C2F, cb0 + C2F));
        }
      }
    }
  }

  float la = la0 + la1, lb = lb0 + lb1;
  la += __shfl_xor_sync(0xffffffffu, la, 1);
  la += __shfl_xor_sync(0xffffffffu, la, 2);
  lb += __shfl_xor_sync(0xffffffffu, lb, 1);
  lb += __shfl_xor_sync(0xffffffffu, lb, 2);
  if (tq == 0) {
    g_lpar[chunk * BB * TT + b * TT + ia] = la;
    g_lpar[chunk * BB * TT + b * TT + ib] = lb;
  }
}

// ---------------- K2b: main pass. grid=(8,128), block=256 ----------------
// Q hoisted to registers; KV pair double-buffer reuses the Q smem region.
// smem: 73728 B (KV buf0@0 buf1@36864; each K[128][144]+V[128][144])
__global__ __launch_bounds__(256, 2) void attnB(float* __restrict__ out) {
  extern __shared__ char S[];
  const uint32_t KVSZ = 36864;
  const int t = threadIdx.x, w = t >> 5, lane = t & 31;
  const int g = lane >> 2, tq = lane & 3;
  const int b = blockIdx.x;
  const int rt = 15 - ((int)blockIdx.y >> 3), chunk = blockIdx.y & 7;
  const int jt0 = chunk * 4;
  const int ntiles = min(4, 2 * rt + 2 - jt0);
  const int i0 = rt * 128;
  const uint32_t sb = su(S);

  float oa[8][4] = {};
  const int ia = i0 + 16 * w + g, ib = ia + 8;
  float* att = out + (size_t)BB * TT * HH + (size_t)b * TT * TT;

  if (ntiles > 0) {
    float lA = 0.0f, lB = 0.0f;
#pragma unroll
    for (int c = 0; c < 8; c++) {
      lA += g_lpar[c * BB * TT + b * TT + ia];
      lB += g_lpar[c * BB * TT + b * TT + ib];
    }
    const float lna = -__log2f(lA), lnb = -__log2f(lB);

    // stage Q through smem, hoist fragments to registers
#pragma unroll
    for (int e = 0; e < 4; e++) {
      int idx = t + e * 256, r = idx >> 3, c8 = idx & 7;   // idx < 1024
      size_t gb = ((size_t)(b * TT + i0 + r) * 64 + c8 * 8) * 2;
      cpa16(sb + (uint32_t)(r * 144 + c8 * 16), (const char*)g_qhi + gb);
    }
    CP_COMMIT(); CP_WAIT0();
    __syncthreads();
    const uint32_t arow = 16 * w + (lane & 15), aoff8 = (lane >> 4) * 8;
    uint32_t qa[4][4];
#pragma unroll
    for (int s = 0; s < 4; s++)
      ldsm4(qa[s], sb + arow * 144 + (s * 16 + aoff8) * 2);
    __syncthreads();   // all warps done with Q smem before KV overwrites

    const int npairs = ntiles >> 1;            // ntiles even (2 or 4)
    // first KV pair -> buf0 (@0)
    {
      const int j0 = jt0 * 64;
#pragma unroll
      for (int e = 0; e < 4; e++) {
        int idx = t + e * 256, r = idx >> 3, c8 = idx & 7;  // idx < 1024
        size_t gb = ((size_t)(b * TT + j0 + r) * 64 + c8 * 8) * 2;
        uint32_t off = (uint32_t)(r * 144 + c8 * 16);
        cpa16(sb + off,         (const char*)g_khi + gb);
        cpa16(sb + off + 18432, (const char*)g_vhi + gb);
      }
    }
    CP_COMMIT();

    const uint32_t brow = (lane & 7) + ((lane >> 4) & 1) * 8;
    const uint32_t boff8 = ((lane >> 3) & 1) * 8;
    const uint32_t vrow = (lane & 7) + ((lane >> 3) & 1) * 8;
    const uint32_t voff8 = ((lane >> 4) & 1) * 8;

    for (int it = 0; it < npairs; it++) {
      CP_WAIT0();
      __syncthreads();

      if (it + 1 < npairs) {
        const int jn = (jt0 + 2 * (it + 1)) * 64;
        const uint32_t nb = ((it + 1) & 1) * KVSZ;
#pragma unroll
        for (int e = 0; e < 4; e++) {
          int idx = t + e * 256, r = idx >> 3, c8 = idx & 7;
          size_t gb = ((size_t)(b * TT + jn + r) * 64 + c8 * 8) * 2;
          uint32_t off = nb + (uint32_t)(r * 144 + c8 * 16);
          cpa16(sb + off,         (const char*)g_khi + gb);
          cpa16(sb + off + 18432, (const char*)g_vhi + gb);
        }
      }
      CP_COMMIT();

      const uint32_t buf = (it & 1) * KVSZ;

#pragma unroll
      for (int half = 0; half < 2; half++) {
        const int j0 = (jt0 + 2 * it + half) * 64;
        const uint32_t KB = buf + half * 9216;
        const uint32_t VB = buf + 18432 + half * 9216;

        float sa[8][4] = {};
#pragma unroll
        for (int s = 0; s < 4; s++) {
#pragma unroll
          for (int p = 0; p < 4; p++) {
            uint32_t bh[4];
            ldsm4(bh, sb + KB + (p * 16 + brow) * 144 + (s * 16 + boff8) * 2);
            mma16816h(sa[2*p],   qa[s], bh[0], bh[1]);
            mma16816h(sa[2*p+1], qa[s], bh[2], bh[3]);
          }
        }

        if (j0 + 64 <= i0) {
#pragma unroll
          for (int nf = 0; nf < 8; nf++) {
            int j = j0 + nf * 8 + tq * 2;
            float ca0 = fmaf((float)(j - ia), C2F, lna);
            float cb0 = fmaf((float)(j - ib), C2F, lnb);
            float p00 = exp2f(fmaf(sa[nf][0], C2F, ca0));
            float p01 = exp2f(fmaf(sa[nf][1], C2F, ca0 + C2F));
            float p10 = exp2f(fmaf(sa[nf][2], C2F, cb0));
            float p11 = exp2f(fmaf(sa[nf][3], C2F, cb0 + C2F));
            stg2cs(att + (size_t)ia * TT + j, p00, p01);
            stg2cs(att + (size_t)ib * TT + j, p10, p11);
            sa[nf][0] = p00; sa[nf][1] = p01; sa[nf][2] = p10; sa[nf][3] = p11;
          }
        } else {
#pragma unroll
          for (int nf = 0; nf < 8; nf++) {
            int j = j0 + nf * 8 + tq * 2;
            float ca0 = fmaf((float)(j - ia), C2F, lna);
            float cb0 = fmaf((float)(j - ib), C2F, lnb);
            float p00 = (j     <= ia) ? exp2f(fmaf(sa[nf][0], C2F, ca0)) : 0.0f;
            float p01 = (j + 1 <= ia) ? exp2f(fmaf(sa[nf][1], C2F, ca0 + C2F)) : 0.0f;
            float p10 = (j     <= ib) ? exp2f(fmaf(sa[nf][2], C2F, cb0)) : 0.0f;
            float p11 = (j + 1 <= ib) ? exp2f(fmaf(sa[nf][3], C2F, cb0 + C2F)) : 0.0f;
            stg2cs(att + (size_t)ia * TT + j, p00, p01);
            stg2cs(att + (size_t)ib * TT + j, p10, p11);
            sa[nf][0] = p00; sa[nf][1] = p01; sa[nf][2] = p10; sa[nf][3] = p11;
          }
        }

#pragma unroll
        for (int s2 = 0; s2 < 4; s2++) {
          uint32_t ah[4];
          ah[0] = packh(sa[2*s2][0],   sa[2*s2][1]);
          ah[1] = packh(sa[2*s2][2],   sa[2*s2][3]);
          ah[2] = packh(sa[2*s2+1][0], sa[2*s2+1][1]);
          ah[3] = packh(sa[2*s2+1][2], sa[2*s2+1][3]);
#pragma unroll
          for (int p = 0; p < 4; p++) {
            uint32_t bh[4];
            ldsm4t(bh, sb + VB + (s2 * 16 + vrow) * 144 + (p * 16 + voff8) * 2);
            mma16816h(oa[2*p],   ah, bh[0], bh[1]);
            mma16816h(oa[2*p+1], ah, bh[2], bh[3]);
          }
        }
      }
    }

    float* opA = out + ((size_t)b * TT + ia) * HH;
    float* opB = out + ((size_t)b * TT + ib) * HH;
#pragma unroll
    for (int nf = 0; nf < 8; nf++) {
      int c = nf * 8 + tq * 2;
      atomicAdd(opA + c,     oa[nf][0]);
      atomicAdd(opA + c + 1, oa[nf][1]);
      atomicAdd(opB + c,     oa[nf][2]);
      atomicAdd(opB + c + 1, oa[nf][3]);
    }
  }

  // ---- zero-fill the strictly-upper part of this block's 256-col strip ----
  {
    const int jf0 = max(jt0, 2 * rt + 2);
    const int nf4 = (jt0 + 4 - jf0) * 16;
    if (nf4 > 0) {
      const float4 z = make_float4(0, 0, 0, 0);
      float4* a4 = (float4*)att;
      for (int r = w; r < 128; r += 8)
        for (int c = lane; c < nf4; c += 32)
          __stcs(&a4[(size_t)(i0 + r) * 512 + jf0 * 16 + c], z);
    }
  }
}

// ---------------------------------------------------------------------------
extern "C" void kernel_launch(void* const* d_in, const int* in_sizes, int n_in,
                              void* d_out, int out_size) {
  const float* x  = (const float*)d_in[0];
  const float* Wq = (const float*)d_in[1];
  const float* Wk = (const float*)d_in[2];
  const float* Wv = (const float*)d_in[3];
  float* out = (float*)d_out;

  k0<<<384, 256>>>(Wq, Wk, Wv);
  kz<<<1024, 256>>>(out);   // zero out-head (atomicAdd target)

  cudaFuncSetAttribute(qkv, cudaFuncAttributeMaxDynamicSharedMemorySize, 55296);
  qkv<<<dim3(128, 3), 256, 55296>>>(x);

  cudaFuncSetAttribute(attnA, cudaFuncAttributeMaxDynamicSharedMemorySize, 18432);
  attnA<<<dim3(8, 128), 256, 18432>>>();

  cudaFuncSetAttribute(attnB, cudaFuncAttributeMaxDynamicSharedMemorySize, 73728);
  cudaFuncSetAttribute(attnB, cudaFuncAttributePreferredSharedMemoryCarveout,
                       cudaSharedmemCarveoutMaxShared);
  attnB<<<dim3(8, 128), 256, 73728>>>(out);
}

// round 16
// speedup vs baseline: 1.1062x; 1.1062x over previous
#include <cuda_runtime.h>
#include <cuda_bf16.h>
#include <cuda_fp16.h>
#include <stdint.h>

#define BB 8
#define TT 2048
#define CC 512
#define HH 64
#define SCALEF 0.044194173824159216f   // 512^-0.5
#define C2F    0.063762484904288f      // SCALEF * log2(e)

// ---------------- scratch (device globals: allocation-free) ----------------
__device__ __half g_qhi[BB*TT*HH];                    // fp16 (1-term S)
__device__ __half g_khi[BB*TT*HH];                    // fp16, hi only
__device__ __half g_vhi[BB*TT*HH];                    // fp16, hi only
__device__ __nv_bfloat16 g_wthi[3*HH*CC], g_wtlo[3*HH*CC];   // [w][h][c]
__device__ float g_lpar[8*BB*TT];

// ---------------- helpers ----------------
__device__ __forceinline__ uint32_t su(const void* p) {
  uint32_t a;
  asm("{ .reg .u64 t; cvta.to.shared.u64 t, %1; cvt.u32.u64 %0, t; }" : "=r"(a) : "l"(p));
  return a;
}
__device__ __forceinline__ void ldsm4(uint32_t* r, uint32_t a) {
  asm volatile("ldmatrix.sync.aligned.m8n8.x4.shared.b16 {%0,%1,%2,%3}, [%4];"
    : "=r"(r[0]), "=r"(r[1]), "=r"(r[2]), "=r"(r[3]) : "r"(a));
}
__device__ __forceinline__ void ldsm4t(uint32_t* r, uint32_t a) {
  asm volatile("ldmatrix.sync.aligned.m8n8.x4.trans.shared.b16 {%0,%1,%2,%3}, [%4];"
    : "=r"(r[0]), "=r"(r[1]), "=r"(r[2]), "=r"(r[3]) : "r"(a));
}
__device__ __forceinline__ void mma16816(float* d, const uint32_t* a, uint32_t b0, uint32_t b1) {
  asm volatile("mma.sync.aligned.m16n8k16.row.col.f32.bf16.bf16.f32 "
    "{%0,%1,%2,%3}, {%4,%5,%6,%7}, {%8,%9}, {%0,%1,%2,%3};"
    : "+f"(d[0]), "+f"(d[1]), "+f"(d[2]), "+f"(d[3])
    : "r"(a[0]), "r"(a[1]), "r"(a[2]), "r"(a[3]), "r"(b0), "r"(b1));
}
__device__ __forceinline__ void mma16816h(float* d, const uint32_t* a, uint32_t b0, uint32_t b1) {
  asm volatile("mma.sync.aligned.m16n8k16.row.col.f32.f16.f16.f32 "
    "{%0,%1,%2,%3}, {%4,%5,%6,%7}, {%8,%9}, {%0,%1,%2,%3};"
    : "+f"(d[0]), "+f"(d[1]), "+f"(d[2]), "+f"(d[3])
    : "r"(a[0]), "r"(a[1]), "r"(a[2]), "r"(a[3]), "r"(b0), "r"(b1));
}
__device__ __forceinline__ void split_pack(float a, float b, uint32_t& hi, uint32_t& lo) {
  __nv_bfloat162 h = __floats2bfloat162_rn(a, b);
  __nv_bfloat162 l = __floats2bfloat162_rn(a - __bfloat162float(h.x),
                                           b - __bfloat162float(h.y));
  hi = *reinterpret_cast<uint32_t*>(&h);
  lo = *reinterpret_cast<uint32_t*>(&l);
}
__device__ __forceinline__ uint32_t packh(float a, float b) {
  __half2 h = __floats2half2_rn(a, b);
  return *reinterpret_cast<uint32_t*>(&h);
}
__device__ __forceinline__ void cpa16(uint32_t s, const void* g) {
  asm volatile("cp.async.cg.shared.global [%0], [%1], 16;" :: "r"(s), "l"(g) : "memory");
}
__device__ __forceinline__ void stg2cs(float* p, float x, float y) {
  asm volatile("st.global.cs.v2.f32 [%0], {%1, %2};" :: "l"(p), "f"(x), "f"(y) : "memory");
}
#define CP_COMMIT() asm volatile("cp.async.commit_group;" ::: "memory")
#define CP_WAIT0()  asm volatile("cp.async.wait_group 0;" ::: "memory")

// ---------------- K0: weight transpose + split ----------------
__global__ void k0(const float* __restrict__ Wq, const float* __restrict__ Wk,
                   const float* __restrict__ Wv) {
  int idx = blockIdx.x * 256 + threadIdx.x;          // < 3*64*512
  int w = idx >> 15, rem = idx & 32767, h = rem >> 9, c = rem & 511;
  const float* W = (w == 0) ? Wq : ((w == 1) ? Wk : Wv);
  float v = W[(size_t)c * HH + h];
  __nv_bfloat16 hi = __float2bfloat16(v);
  g_wthi[idx] = hi;
  g_wtlo[idx] = __float2bfloat16(v - __bfloat162float(hi));
}

// ---------------- Kz: zero the output head region ----------------
__global__ void kz(float* __restrict__ out) {
  ((float4*)out)[blockIdx.x * 256 + threadIdx.x] = make_float4(0, 0, 0, 0);
}

// ---------------- K1: fused QKV on HMMA. grid=128, block=256 ----------------
__global__ __launch_bounds__(256, 1) void qkv(const float* __restrict__ x) {
  extern __shared__ char S[];
  const uint32_t XH = 0, XL = 18432, WB = 36864;
  const int t = threadIdx.x, w = t >> 5, lane = t & 31;
  const int g = lane >> 2, tq = lane & 3;
  const int row0 = blockIdx.x * 128;
  const uint32_t sb = su(S);
  const uint32_t arow = 16 * w + (lane & 15), aoff8 = (lane >> 4) * 8;
  const uint32_t brow = (lane & 7) + ((lane >> 4) & 1) * 8;
  const uint32_t boff8 = ((lane >> 3) & 1) * 8;

  float acc[3][8][4] = {};

  for (int kci = 0; kci < 8; kci++) {
    __syncthreads();
#pragma unroll
    for (int e = 0; e < 16; e++) {
      int idx = t + e * 256, r = idx >> 5, cp = idx & 31;
      float2 xv = *(const float2*)(x + (size_t)(row0 + r) * CC + kci * 64 + cp * 2);
      uint32_t hi, lo; split_pack(xv.x, xv.y, hi, lo);
      uint32_t off = (uint32_t)(r * 144 + cp * 4);
      *(uint32_t*)(S + XH + off) = hi;
      *(uint32_t*)(S + XL + off) = lo;
    }
#pragma unroll
    for (int e = 0; e < 24; e++) {
      int idx = t + e * 256;                 // < 6144
      int o = idx >> 11, r2 = idx & 2047, h = r2 >> 5, cp = r2 & 31;
      uint32_t gi = (uint32_t)(o * 16384 + h * 256 + kci * 32 + cp);
      uint32_t off = WB + o * 18432 + h * 144 + cp * 4;
      *(uint32_t*)(S + off)        = ((const uint32_t*)g_wthi)[gi];
      *(uint32_t*)(S + off + 9216) = ((const uint32_t*)g_wtlo)[gi];
    }
    __syncthreads();

#pragma unroll
    for (int s = 0; s < 4; s++) {
      uint32_t ah[4], al[4];
      uint32_t qa = sb + XH + arow * 144 + (s * 16 + aoff8) * 2;
      ldsm4(ah, qa);
      ldsm4(al, qa + XL);
#pragma unroll
      for (int o = 0; o < 3; o++) {
        uint32_t base = sb + WB + o * 18432;
#pragma unroll
        for (int p = 0; p < 4; p++) {
          uint32_t bh[4], bl[4];
          uint32_t ka = base + (p * 16 + brow) * 144 + (s * 16 + boff8) * 2;
          ldsm4(bh, ka);
          ldsm4(bl, ka + 9216);
          mma16816(acc[o][2*p],   ah, bh[0], bh[1]);
          mma16816(acc[o][2*p],   al, bh[0], bh[1]);
          mma16816(acc[o][2*p],   ah, bl[0], bl[1]);
          mma16816(acc[o][2*p+1], ah, bh[2], bh[3]);
          mma16816(acc[o][2*p+1], al, bh[2], bh[3]);
          mma16816(acc[o][2*p+1], ah, bl[2], bl[3]);
        }
      }
    }
  }

  const size_t ra = (size_t)(row0 + 16 * w + g), rb = ra + 8;
  {
    uint32_t* dq = (uint32_t*)g_qhi;
    uint32_t* dk = (uint32_t*)g_khi;
    uint32_t* dv = (uint32_t*)g_vhi;
#pragma unroll
    for (int nf = 0; nf < 8; nf++) {
      dq[ra * 32 + nf * 4 + tq] = packh(acc[0][nf][0], acc[0][nf][1]);
      dq[rb * 32 + nf * 4 + tq] = packh(acc[0][nf][2], acc[0][nf][3]);
      dk[ra * 32 + nf * 4 + tq] = packh(acc[1][nf][0], acc[1][nf][1]);
      dk[rb * 32 + nf * 4 + tq] = packh(acc[1][nf][2], acc[1][nf][3]);
      dv[ra * 32 + nf * 4 + tq] = packh(acc[2][nf][0], acc[2][nf][1]);
      dv[rb * 32 + nf * 4 + tq] = packh(acc[2][nf][2], acc[2][nf][3]);
    }
  }
}

// ---------------- K2a: row-sum pass. grid=(8,128), block=256 ----------------
// Q hoisted to registers; K double-buffer reuses the Q smem region.
// smem: 18432 B total (Q staging, then K buf0@0 / buf1@9216)
__global__ __launch_bounds__(256, 3) void attnA() {
  extern __shared__ char S[];
  const uint32_t KSZ = 9216;
  const int t = threadIdx.x, w = t >> 5, lane = t & 31;
  const int g = lane >> 2, tq = lane & 3;
  const int b = blockIdx.x;
  const int rt = 15 - ((int)blockIdx.y >> 3), chunk = blockIdx.y & 7;
  const int jt0 = chunk * 4;
  const int ntiles = min(4, 2 * rt + 2 - jt0);
  const int i0 = rt * 128;
  const uint32_t sb = su(S);

  float la0 = 0.0f, la1 = 0.0f, lb0 = 0.0f, lb1 = 0.0f;
  const int ia = i0 + 16 * w + g, ib = ia + 8;

  if (ntiles > 0) {
    // stage Q through smem, hoist fragments to registers
#pragma unroll
    for (int e = 0; e < 4; e++) {
      int idx = t + e * 256, r = idx >> 3, c8 = idx & 7;   // idx < 1024
      size_t gb = ((size_t)(b * TT + i0 + r) * 64 + c8 * 8) * 2;
      cpa16(sb + (uint32_t)(r * 144 + c8 * 16), (const char*)g_qhi + gb);
    }
    CP_COMMIT(); CP_WAIT0();
    __syncthreads();
    const uint32_t arow = 16 * w + (lane & 15), aoff8 = (lane >> 4) * 8;
    uint32_t qa[4][4];
#pragma unroll
    for (int s = 0; s < 4; s++)
      ldsm4(qa[s], sb + arow * 144 + (s * 16 + aoff8) * 2);
    __syncthreads();   // all warps done with Q smem before K overwrites

    // first K tile -> buf0 (@0)
    {
      const int j0 = jt0 * 64;
#pragma unroll
      for (int e = 0; e < 2; e++) {
        int idx = t + e * 256, r = idx >> 3, c8 = idx & 7;  // idx < 512
        size_t gb = ((size_t)(b * TT + j0 + r) * 64 + c8 * 8) * 2;
        cpa16(sb + (uint32_t)(r * 144 + c8 * 16), (const char*)g_khi + gb);
      }
    }
    CP_COMMIT();

    const uint32_t brow = (lane & 7) + ((lane >> 4) & 1) * 8;
    const uint32_t boff8 = ((lane >> 3) & 1) * 8;

    for (int ti = 0; ti < ntiles; ti++) {
      const int j0 = (jt0 + ti) * 64;
      CP_WAIT0();
      __syncthreads();

      if (ti + 1 < ntiles) {
        const int jn = (jt0 + ti + 1) * 64;
        const uint32_t nb = ((ti + 1) & 1) * KSZ;
#pragma unroll
        for (int e = 0; e < 2; e++) {
          int idx = t + e * 256, r = idx >> 3, c8 = idx & 7;
          size_t gb = ((size_t)(b * TT + jn + r) * 64 + c8 * 8) * 2;
          cpa16(sb + nb + (uint32_t)(r * 144 + c8 * 16), (const char*)g_khi + gb);
        }
      }
      CP_COMMIT();

      const uint32_t KB = (ti & 1) * KSZ;

      float sa[8][4] = {};
#pragma unroll
      for (int s = 0; s < 4; s++) {
#pragma unroll
        for (int p = 0; p < 4; p++) {
          uint32_t bh[4];
          ldsm4(bh, sb + KB + (p * 16 + brow) * 144 + (s * 16 + boff8) * 2);
          mma16816h(sa[2*p],   qa[s], bh[0], bh[1]);
          mma16816h(sa[2*p+1], qa[s], bh[2], bh[3]);
        }
      }

      if (j0 + 64 <= i0) {
#pragma unroll
        for (int nf = 0; nf < 8; nf++) {
          int j = j0 + nf * 8 + tq * 2;
          float ca0 = (float)(j - ia) * C2F, cb0 = (float)(j - ib) * C2F;
          if (nf & 1) {
            la1 += exp2f(fmaf(sa[nf][0], C2F, ca0));
            la1 += exp2f(fmaf(sa[nf][1], C2F, ca0 + C2F));
            lb1 += exp2f(fmaf(sa[nf][2], C2F, cb0));
            lb1 += exp2f(fmaf(sa[nf][3], C2F, cb0 + C2F));
          } else {
            la0 += exp2f(fmaf(sa[nf][0], C2F, ca0));
            la0 += exp2f(fmaf(sa[nf][1], C2F, ca0 + C2F));
            lb0 += exp2f(fmaf(sa[nf][2], C2F, cb0));
            lb0 += exp2f(fmaf(sa[nf][3], C2F, cb0 + C2F));
          }
        }
      } else {
#pragma unroll
        for (int nf = 0; nf < 8; nf++) {
          int j = j0 + nf * 8 + tq * 2;
          float ca0 = (float)(j - ia) * C2F, cb0 = (float)(j - ib) * C2F;
          if (j     <= ia) la0 += exp2f(fmaf(sa[nf][0], C2F, ca0));
          if (j + 1 <= ia) la1 += exp2f(fmaf(sa[nf][1], C2F, ca0 + C2F));
          if (j     <= ib) lb0 += exp2f(fmaf(sa[nf][2], C2F, cb0));
          if (j + 1 <= ib) lb1 += exp2f(fmaf(sa[nf][3], C2F, cb0 + C2F));
        }
      }
    }
  }

  float la = la0 + la1, lb = lb0 + lb1;
  la += __shfl_xor_sync(0xffffffffu, la, 1);
  la += __shfl_xor_sync(0xffffffffu, la, 2);
  lb += __shfl_xor_sync(0xffffffffu, lb, 1);
  lb += __shfl_xor_sync(0xffffffffu, lb, 2);
  if (tq == 0) {
    g_lpar[chunk * BB * TT + b * TT + ia] = la;
    g_lpar[chunk * BB * TT + b * TT + ib] = lb;
  }
}

// ---------------- K2b: main pass. grid=(8,128), block=256 ----------------
// Writes FINAL normalized attention (log2(1/l) folded into the exponent),
// accumulates normalized O, atomicAdds into the pre-zeroed out head.
// smem: Qh[128][72]@0 | KV pair buf0@18432 buf1@55296 (92160 B total)
__global__ __launch_bounds__(256, 2) void attnB(float* __restrict__ out) {
  extern __shared__ char S[];
  const uint32_t QH = 0, KV0 = 18432, KVSZ = 36864;
  const int t = threadIdx.x, w = t >> 5, lane = t & 31;
  const int g = lane >> 2, tq = lane & 3;
  const int b = blockIdx.x;
  const int rt = 15 - ((int)blockIdx.y >> 3), chunk = blockIdx.y & 7;
  const int jt0 = chunk * 4;
  const int ntiles = min(4, 2 * rt + 2 - jt0);
  const int i0 = rt * 128;
  const uint32_t sb = su(S);

  float oa[8][4] = {};
  const int ia = i0 + 16 * w + g, ib = ia + 8;
  float* att = out + (size_t)BB * TT * HH + (size_t)b * TT * TT;

  if (ntiles > 0) {
    float lA = 0.0f, lB = 0.0f;
#pragma unroll
    for (int c = 0; c < 8; c++) {
      lA += g_lpar[c * BB * TT + b * TT + ia];
      lB += g_lpar[c * BB * TT + b * TT + ib];
    }
    const float lna = -__log2f(lA), lnb = -__log2f(lB);

    const int npairs = ntiles >> 1;            // ntiles even (2 or 4)
#pragma unroll
    for (int e = 0; e < 4; e++) {
      int idx = t + e * 256, r = idx >> 3, c8 = idx & 7;   // idx < 1024
      size_t gb = ((size_t)(b * TT + i0 + r) * 64 + c8 * 8) * 2;
      cpa16(sb + QH + (uint32_t)(r * 144 + c8 * 16), (const char*)g_qhi + gb);
    }
    {
      const int j0 = jt0 * 64;
#pragma unroll
      for (int e = 0; e < 4; e++) {
        int idx = t + e * 256, r = idx >> 3, c8 = idx & 7;  // idx < 1024
        size_t gb = ((size_t)(b * TT + j0 + r) * 64 + c8 * 8) * 2;
        uint32_t off = KV0 + (uint32_t)(r * 144 + c8 * 16);
        cpa16(sb + off,         (const char*)g_khi + gb);
        cpa16(sb + off + 18432, (const char*)g_vhi + gb);
      }
    }
    CP_COMMIT();

    const uint32_t arow = 16 * w + (lane & 15), aoff8 = (lane >> 4) * 8;
    const uint32_t brow = (lane & 7) + ((lane >> 4) & 1) * 8;
    const uint32_t boff8 = ((lane >> 3) & 1) * 8;
    const uint32_t vrow = (lane & 7) + ((lane >> 3) & 1) * 8;
    const uint32_t voff8 = ((lane >> 4) & 1) * 8;

    for (int it = 0; it < npairs; it++) {
      CP_WAIT0();
      __syncthreads();

      if (it + 1 < npairs) {
        const int jn = (jt0 + 2 * (it + 1)) * 64;
        const uint32_t nb = KV0 + ((it + 1) & 1) * KVSZ;
#pragma unroll
        for (int e = 0; e < 4; e++) {
          int idx = t + e * 256, r = idx >> 3, c8 = idx & 7;
          size_t gb = ((size_t)(b * TT + jn + r) * 64 + c8 * 8) * 2;
          uint32_t off = nb + (uint32_t)(r * 144 + c8 * 16);
          cpa16(sb + off,         (const char*)g_khi + gb);
          cpa16(sb + off + 18432, (const char*)g_vhi + gb);
        }
      }
      CP_COMMIT();

      const uint32_t buf = KV0 + (it & 1) * KVSZ;

#pragma unroll
      for (int half = 0; half < 2; half++) {
        const int j0 = (jt0 + 2 * it + half) * 64;
        const uint32_t KB = buf + half * 9216;
        const uint32_t VB = buf + 18432 + half * 9216;

        float sa[8][4] = {};
#pragma unroll
        for (int s = 0; s < 4; s++) {
          uint32_t ah[4];
          ldsm4(ah, sb + QH + arow * 144 + (s * 16 + aoff8) * 2);
#pragma unroll
          for (int p = 0; p < 4; p++) {
            uint32_t bh[4];
            ldsm4(bh, sb + KB + (p * 16 + brow) * 144 + (s * 16 + boff8) * 2);
            mma16816h(sa[2*p],   ah, bh[0], bh[1]);
            mma16816h(sa[2*p+1], ah, bh[2], bh[3]);
          }
        }

        if (j0 + 64 <= i0) {
          // full tile: no causal predicates
#pragma unroll
          for (int nf = 0; nf < 8; nf++) {
            int j = j0 + nf * 8 + tq * 2;
            float ca0 = fmaf((float)(j - ia), C2F, lna);
            float cb0 = fmaf((float)(j - ib), C2F, lnb);
            float p00 = exp2f(fmaf(sa[nf][0], C2F, ca0));
            float p01 = exp2f(fmaf(sa[nf][1], C2F, ca0 + C2F));
            float p10 = exp2f(fmaf(sa[nf][2], C2F, cb0));
            float p11 = exp2f(fmaf(sa[nf][3], C2F, cb0 + C2F));
            stg2cs(att + (size_t)ia * TT + j, p00, p01);
            stg2cs(att + (size_t)ib * TT + j, p10, p11);
            sa[nf][0] = p00; sa[nf][1] = p01; sa[nf][2] = p10; sa[nf][3] = p11;
          }
        } else {
#pragma unroll
          for (int nf = 0; nf < 8; nf++) {
            int j = j0 + nf * 8 + tq * 2;
            float ca0 = fmaf((float)(j - ia), C2F, lna);
            float cb0 = fmaf((float)(j - ib), C2F, lnb);
            float p00 = (j     <= ia) ? exp2f(fmaf(sa[nf][0], C2F, ca0)) : 0.0f;
            float p01 = (j + 1 <= ia) ? exp2f(fmaf(sa[nf][1], C2F, ca0 + C2F)) : 0.0f;
            float p10 = (j     <= ib) ? exp2f(fmaf(sa[nf][2], C2F, cb0)) : 0.0f;
            float p11 = (j + 1 <= ib) ? exp2f(fmaf(sa[nf][3], C2F, cb0 + C2F)) : 0.0f;
            stg2cs(att + (size_t)ia * TT + j, p00, p01);
            stg2cs(att + (size_t)ib * TT + j, p10, p11);
            sa[nf][0] = p00; sa[nf][1] = p01; sa[nf][2] = p10; sa[nf][3] = p11;
          }
        }

#pragma unroll
        for (int s2 = 0; s2 < 4; s2++) {
          uint32_t ah[4];
          ah[0] = packh(sa[2*s2][0],   sa[2*s2][1]);
          ah[1] = packh(sa[2*s2][2],   sa[2*s2][3]);
          ah[2] = packh(sa[2*s2+1][0], sa[2*s2+1][1]);
          ah[3] = packh(sa[2*s2+1][2], sa[2*s2+1][3]);
#pragma unroll
          for (int p = 0; p < 4; p++) {
            uint32_t bh[4];
            ldsm4t(bh, sb + VB + (s2 * 16 + vrow) * 144 + (p * 16 + voff8) * 2);
            mma16816h(oa[2*p],   ah, bh[0], bh[1]);
            mma16816h(oa[2*p+1], ah, bh[2], bh[3]);
          }
        }
      }
    }

    float* opA = out + ((size_t)b * TT + ia) * HH;
    float* opB = out + ((size_t)b * TT + ib) * HH;
#pragma unroll
    for (int nf = 0; nf < 8; nf++) {
      int c = nf * 8 + tq * 2;
      atomicAdd(opA + c,     oa[nf][0]);
      atomicAdd(opA + c + 1, oa[nf][1]);
      atomicAdd(opB + c,     oa[nf][2]);
      atomicAdd(opB + c + 1, oa[nf][3]);
    }
  }

  // ---- zero-fill the strictly-upper part of this block's 256-col strip ----
  {
    const int jf0 = max(jt0, 2 * rt + 2);
    const int nf4 = (jt0 + 4 - jf0) * 16;
    if (nf4 > 0) {
      const float4 z = make_float4(0, 0, 0, 0);
      float4* a4 = (float4*)att;
      for (int r = w; r < 128; r += 8)
        for (int c = lane; c < nf4; c += 32)
          __stcs(&a4[(size_t)(i0 + r) * 512 + jf0 * 16 + c], z);
    }
  }
}

// ---------------------------------------------------------------------------
extern "C" void kernel_launch(void* const* d_in, const int* in_sizes, int n_in,
                              void* d_out, int out_size) {
  const float* x  = (const float*)d_in[0];
  const float* Wq = (const float*)d_in[1];
  const float* Wk = (const float*)d_in[2];
  const float* Wv = (const float*)d_in[3];
  float* out = (float*)d_out;

  k0<<<384, 256>>>(Wq, Wk, Wv);
  kz<<<1024, 256>>>(out);   // zero out-head (atomicAdd target)

  cudaFuncSetAttribute(qkv, cudaFuncAttributeMaxDynamicSharedMemorySize, 92160);
  qkv<<<128, 256, 92160>>>(x);

  cudaFuncSetAttribute(attnA, cudaFuncAttributeMaxDynamicSharedMemorySize, 18432);
  attnA<<<dim3(8, 128), 256, 18432>>>();

  cudaFuncSetAttribute(attnB, cudaFuncAttributeMaxDynamicSharedMemorySize, 92160);
  cudaFuncSetAttribute(attnB, cudaFuncAttributePreferredSharedMemoryCarveout,
                       cudaSharedmemCarveoutMaxShared);
  attnB<<<dim3(8, 128), 256, 92160>>>(out);
}

// round 17
// speedup vs baseline: 1.1541x; 1.0432x over previous
#include <cuda_runtime.h>
#include <cuda_bf16.h>
#include <cuda_fp16.h>
#include <stdint.h>

#define BB 8
#define TT 2048
#define CC 512
#define HH 64
#define SCALEF 0.044194173824159216f   // 512^-0.5
#define C2F    0.063762484904288f      // SCALEF * log2(e)

// ---------------- scratch (device globals: allocation-free) ----------------
__device__ __half g_qhi[BB*TT*HH];                    // fp16 (1-term S)
__device__ __half g_khi[BB*TT*HH];                    // fp16, hi only
__device__ __half g_vhi[BB*TT*HH];                    // fp16, hi only
__device__ __nv_bfloat16 g_wthi[3*HH*CC], g_wtlo[3*HH*CC];   // [w][h][c]
__device__ float g_lpar[8*BB*TT];

// ---------------- helpers ----------------
__device__ __forceinline__ uint32_t su(const void* p) {
  uint32_t a;
  asm("{ .reg .u64 t; cvta.to.shared.u64 t, %1; cvt.u32.u64 %0, t; }" : "=r"(a) : "l"(p));
  return a;
}
__device__ __forceinline__ void ldsm4(uint32_t* r, uint32_t a) {
  asm volatile("ldmatrix.sync.aligned.m8n8.x4.shared.b16 {%0,%1,%2,%3}, [%4];"
    : "=r"(r[0]), "=r"(r[1]), "=r"(r[2]), "=r"(r[3]) : "r"(a));
}
__device__ __forceinline__ void ldsm4t(uint32_t* r, uint32_t a) {
  asm volatile("ldmatrix.sync.aligned.m8n8.x4.trans.shared.b16 {%0,%1,%2,%3}, [%4];"
    : "=r"(r[0]), "=r"(r[1]), "=r"(r[2]), "=r"(r[3]) : "r"(a));
}
__device__ __forceinline__ void mma16816(float* d, const uint32_t* a, uint32_t b0, uint32_t b1) {
  asm volatile("mma.sync.aligned.m16n8k16.row.col.f32.bf16.bf16.f32 "
    "{%0,%1,%2,%3}, {%4,%5,%6,%7}, {%8,%9}, {%0,%1,%2,%3};"
    : "+f"(d[0]), "+f"(d[1]), "+f"(d[2]), "+f"(d[3])
    : "r"(a[0]), "r"(a[1]), "r"(a[2]), "r"(a[3]), "r"(b0), "r"(b1));
}
__device__ __forceinline__ void mma16816h(float* d, const uint32_t* a, uint32_t b0, uint32_t b1) {
  asm volatile("mma.sync.aligned.m16n8k16.row.col.f32.f16.f16.f32 "
    "{%0,%1,%2,%3}, {%4,%5,%6,%7}, {%8,%9}, {%0,%1,%2,%3};"
    : "+f"(d[0]), "+f"(d[1]), "+f"(d[2]), "+f"(d[3])
    : "r"(a[0]), "r"(a[1]), "r"(a[2]), "r"(a[3]), "r"(b0), "r"(b1));
}
__device__ __forceinline__ void split_pack(float a, float b, uint32_t& hi, uint32_t& lo) {
  __nv_bfloat162 h = __floats2bfloat162_rn(a, b);
  __nv_bfloat162 l = __floats2bfloat162_rn(a - __bfloat162float(h.x),
                                           b - __bfloat162float(h.y));
  hi = *reinterpret_cast<uint32_t*>(&h);
  lo = *reinterpret_cast<uint32_t*>(&l);
}
__device__ __forceinline__ uint32_t packh(float a, float b) {
  __half2 h = __floats2half2_rn(a, b);
  return *reinterpret_cast<uint32_t*>(&h);
}
__device__ __forceinline__ void cpa16(uint32_t s, const void* g) {
  asm volatile("cp.async.cg.shared.global [%0], [%1], 16;" :: "r"(s), "l"(g) : "memory");
}
__device__ __forceinline__ void stg2cs(float* p, float x, float y) {
  asm volatile("st.global.cs.v2.f32 [%0], {%1, %2};" :: "l"(p), "f"(x), "f"(y) : "memory");
}
#define CP_COMMIT() asm volatile("cp.async.commit_group;" ::: "memory")
#define CP_WAIT0()  asm volatile("cp.async.wait_group 0;" ::: "memory")

// ---------------- K0: weight transpose + split ----------------
__global__ void k0(const float* __restrict__ Wq, const float* __restrict__ Wk,
                   const float* __restrict__ Wv) {
  int idx = blockIdx.x * 256 + threadIdx.x;          // < 3*64*512
  int w = idx >> 15, rem = idx & 32767, h = rem >> 9, c = rem & 511;
  const float* W = (w == 0) ? Wq : ((w == 1) ? Wk : Wv);
  float v = W[(size_t)c * HH + h];
  __nv_bfloat16 hi = __float2bfloat16(v);
  g_wthi[idx] = hi;
  g_wtlo[idx] = __float2bfloat16(v - __bfloat162float(hi));
}

// ---------------- Kz: zero the output head region ----------------
__global__ void kz(float* __restrict__ out) {
  ((float4*)out)[blockIdx.x * 256 + threadIdx.x] = make_float4(0, 0, 0, 0);
}

// ---------------- K1: fused QKV on HMMA. grid=128, block=256 ----------------
__global__ __launch_bounds__(256, 1) void qkv(const float* __restrict__ x) {
  extern __shared__ char S[];
  const uint32_t XH = 0, XL = 18432, WB = 36864;
  const int t = threadIdx.x, w = t >> 5, lane = t & 31;
  const int g = lane >> 2, tq = lane & 3;
  const int row0 = blockIdx.x * 128;
  const uint32_t sb = su(S);
  const uint32_t arow = 16 * w + (lane & 15), aoff8 = (lane >> 4) * 8;
  const uint32_t brow = (lane & 7) + ((lane >> 4) & 1) * 8;
  const uint32_t boff8 = ((lane >> 3) & 1) * 8;

  float acc[3][8][4] = {};

  for (int kci = 0; kci < 8; kci++) {
    __syncthreads();
#pragma unroll
    for (int e = 0; e < 16; e++) {
      int idx = t + e * 256, r = idx >> 5, cp = idx & 31;
      float2 xv = *(const float2*)(x + (size_t)(row0 + r) * CC + kci * 64 + cp * 2);
      uint32_t hi, lo; split_pack(xv.x, xv.y, hi, lo);
      uint32_t off = (uint32_t)(r * 144 + cp * 4);
      *(uint32_t*)(S + XH + off) = hi;
      *(uint32_t*)(S + XL + off) = lo;
    }
#pragma unroll
    for (int e = 0; e < 24; e++) {
      int idx = t + e * 256;                 // < 6144
      int o = idx >> 11, r2 = idx & 2047, h = r2 >> 5, cp = r2 & 31;
      uint32_t gi = (uint32_t)(o * 16384 + h * 256 + kci * 32 + cp);
      uint32_t off = WB + o * 18432 + h * 144 + cp * 4;
      *(uint32_t*)(S + off)        = ((const uint32_t*)g_wthi)[gi];
      *(uint32_t*)(S + off + 9216) = ((const uint32_t*)g_wtlo)[gi];
    }
    __syncthreads();

#pragma unroll
    for (int s = 0; s < 4; s++) {
      uint32_t ah[4], al[4];
      uint32_t qa = sb + XH + arow * 144 + (s * 16 + aoff8) * 2;
      ldsm4(ah, qa);
      ldsm4(al, qa + XL);
#pragma unroll
      for (int o = 0; o < 3; o++) {
        uint32_t base = sb + WB + o * 18432;
#pragma unroll
        for (int p = 0; p < 4; p++) {
          uint32_t bh[4], bl[4];
          uint32_t ka = base + (p * 16 + brow) * 144 + (s * 16 + boff8) * 2;
          ldsm4(bh, ka);
          ldsm4(bl, ka + 9216);
          mma16816(acc[o][2*p],   ah, bh[0], bh[1]);
          mma16816(acc[o][2*p],   al, bh[0], bh[1]);
          mma16816(acc[o][2*p],   ah, bl[0], bl[1]);
          mma16816(acc[o][2*p+1], ah, bh[2], bh[3]);
          mma16816(acc[o][2*p+1], al, bh[2], bh[3]);
          mma16816(acc[o][2*p+1], ah, bl[2], bl[3]);
        }
      }
    }
  }

  const size_t ra = (size_t)(row0 + 16 * w + g), rb = ra + 8;
  {
    uint32_t* dq = (uint32_t*)g_qhi;
    uint32_t* dk = (uint32_t*)g_khi;
    uint32_t* dv = (uint32_t*)g_vhi;
#pragma unroll
    for (int nf = 0; nf < 8; nf++) {
      dq[ra * 32 + nf * 4 + tq] = packh(acc[0][nf][0], acc[0][nf][1]);
      dq[rb * 32 + nf * 4 + tq] = packh(acc[0][nf][2], acc[0][nf][3]);
      dk[ra * 32 + nf * 4 + tq] = packh(acc[1][nf][0], acc[1][nf][1]);
      dk[rb * 32 + nf * 4 + tq] = packh(acc[1][nf][2], acc[1][nf][3]);
      dv[ra * 32 + nf * 4 + tq] = packh(acc[2][nf][0], acc[2][nf][1]);
      dv[rb * 32 + nf * 4 + tq] = packh(acc[2][nf][2], acc[2][nf][3]);
    }
  }
}

// ---------------- K2a: row-sum pass. grid=(8,128), block=256 ----------------
// Q in registers; per-p fused S->exp pipeline (8 live S regs).
// smem: 18432 B total (Q staging, then K buf0@0 / buf1@9216)
__global__ __launch_bounds__(256, 4) void attnA() {
  extern __shared__ char S[];
  const uint32_t KSZ = 9216;
  const int t = threadIdx.x, w = t >> 5, lane = t & 31;
  const int g = lane >> 2, tq = lane & 3;
  const int b = blockIdx.x;
  const int rt = 15 - ((int)blockIdx.y >> 3), chunk = blockIdx.y & 7;
  const int jt0 = chunk * 4;
  const int ntiles = min(4, 2 * rt + 2 - jt0);
  const int i0 = rt * 128;
  const uint32_t sb = su(S);

  float la0 = 0.0f, la1 = 0.0f, lb0 = 0.0f, lb1 = 0.0f;
  const int ia = i0 + 16 * w + g, ib = ia + 8;

  if (ntiles > 0) {
    // stage Q through smem, hoist fragments to registers
#pragma unroll
    for (int e = 0; e < 4; e++) {
      int idx = t + e * 256, r = idx >> 3, c8 = idx & 7;   // idx < 1024
      size_t gb = ((size_t)(b * TT + i0 + r) * 64 + c8 * 8) * 2;
      cpa16(sb + (uint32_t)(r * 144 + c8 * 16), (const char*)g_qhi + gb);
    }
    CP_COMMIT(); CP_WAIT0();
    __syncthreads();
    const uint32_t arow = 16 * w + (lane & 15), aoff8 = (lane >> 4) * 8;
    uint32_t qa[4][4];
#pragma unroll
    for (int s = 0; s < 4; s++)
      ldsm4(qa[s], sb + arow * 144 + (s * 16 + aoff8) * 2);
    __syncthreads();   // all warps done with Q smem before K overwrites

    // first K tile -> buf0 (@0)
    {
      const int j0 = jt0 * 64;
#pragma unroll
      for (int e = 0; e < 2; e++) {
        int idx = t + e * 256, r = idx >> 3, c8 = idx & 7;  // idx < 512
        size_t gb = ((size_t)(b * TT + j0 + r) * 64 + c8 * 8) * 2;
        cpa16(sb + (uint32_t)(r * 144 + c8 * 16), (const char*)g_khi + gb);
      }
    }
    CP_COMMIT();

    const uint32_t brow = (lane & 7) + ((lane >> 4) & 1) * 8;
    const uint32_t boff8 = ((lane >> 3) & 1) * 8;

    for (int ti = 0; ti < ntiles; ti++) {
      const int j0 = (jt0 + ti) * 64;
      CP_WAIT0();
      __syncthreads();

      if (ti + 1 < ntiles) {
        const int jn = (jt0 + ti + 1) * 64;
        const uint32_t nb = ((ti + 1) & 1) * KSZ;
#pragma unroll
        for (int e = 0; e < 2; e++) {
          int idx = t + e * 256, r = idx >> 3, c8 = idx & 7;
          size_t gb = ((size_t)(b * TT + jn + r) * 64 + c8 * 8) * 2;
          cpa16(sb + nb + (uint32_t)(r * 144 + c8 * 16), (const char*)g_khi + gb);
        }
      }
      CP_COMMIT();

      const uint32_t KB = (ti & 1) * KSZ;
      const bool full = (j0 + 64 <= i0);

#pragma unroll
      for (int p = 0; p < 4; p++) {
        float s0[4] = {}, s1[4] = {};
#pragma unroll
        for (int s = 0; s < 4; s++) {
          uint32_t bh[4];
          ldsm4(bh, sb + KB + (p * 16 + brow) * 144 + (s * 16 + boff8) * 2);
          mma16816h(s0, qa[s], bh[0], bh[1]);
          mma16816h(s1, qa[s], bh[2], bh[3]);
        }
        int j = j0 + p * 16 + tq * 2;        // nf = 2p
        float ca0 = (float)(j - ia) * C2F, cb0 = (float)(j - ib) * C2F;
        if (full) {
          la0 += exp2f(fmaf(s0[0], C2F, ca0));
          la1 += exp2f(fmaf(s0[1], C2F, ca0 + C2F));
          lb0 += exp2f(fmaf(s0[2], C2F, cb0));
          lb1 += exp2f(fmaf(s0[3], C2F, cb0 + C2F));
          la0 += exp2f(fmaf(s1[0], C2F, ca0 + 8.0f * C2F));
          la1 += exp2f(fmaf(s1[1], C2F, ca0 + 9.0f * C2F));
          lb0 += exp2f(fmaf(s1[2], C2F, cb0 + 8.0f * C2F));
          lb1 += exp2f(fmaf(s1[3], C2F, cb0 + 9.0f * C2F));
        } else {
          if (j     <= ia) la0 += exp2f(fmaf(s0[0], C2F, ca0));
          if (j + 1 <= ia) la1 += exp2f(fmaf(s0[1], C2F, ca0 + C2F));
          if (j     <= ib) lb0 += exp2f(fmaf(s0[2], C2F, cb0));
          if (j + 1 <= ib) lb1 += exp2f(fmaf(s0[3], C2F, cb0 + C2F));
          if (j + 8 <= ia) la0 += exp2f(fmaf(s1[0], C2F, ca0 + 8.0f * C2F));
          if (j + 9 <= ia) la1 += exp2f(fmaf(s1[1], C2F, ca0 + 9.0f * C2F));
          if (j + 8 <= ib) lb0 += exp2f(fmaf(s1[2], C2F, cb0 + 8.0f * C2F));
          if (j + 9 <= ib) lb1 += exp2f(fmaf(s1[3], C2F, cb0 + 9.0f * C2F));
        }
      }
    }
  }

  float la = la0 + la1, lb = lb0 + lb1;
  la += __shfl_xor_sync(0xffffffffu, la, 1);
  la += __shfl_xor_sync(0xffffffffu, la, 2);
  lb += __shfl_xor_sync(0xffffffffu, lb, 1);
  lb += __shfl_xor_sync(0xffffffffu, lb, 2);
  if (tq == 0) {
    g_lpar[chunk * BB * TT + b * TT + ia] = la;
    g_lpar[chunk * BB * TT + b * TT + ib] = lb;
  }
}

// ---------------- K2b: main pass. grid=(8,128), block=256 ----------------
// Q in registers; per-p fused S->exp->store->PV pipeline. Writes FINAL
// normalized attention; atomicAdds O into pre-zeroed out head.
// smem: 73728 B (KV buf0@0 buf1@36864; each K[128][144]@+0 V[128][144]@+18432)
__global__ __launch_bounds__(256, 2) void attnB(float* __restrict__ out) {
  extern __shared__ char S[];
  const uint32_t KVSZ = 36864;
  const int t = threadIdx.x, w = t >> 5, lane = t & 31;
  const int g = lane >> 2, tq = lane & 3;
  const int b = blockIdx.x;
  const int rt = 15 - ((int)blockIdx.y >> 3), chunk = blockIdx.y & 7;
  const int jt0 = chunk * 4;
  const int ntiles = min(4, 2 * rt + 2 - jt0);
  const int i0 = rt * 128;
  const uint32_t sb = su(S);

  float oa[8][4] = {};
  const int ia = i0 + 16 * w + g, ib = ia + 8;
  float* att = out + (size_t)BB * TT * HH + (size_t)b * TT * TT;

  if (ntiles > 0) {
    float lA = 0.0f, lB = 0.0f;
#pragma unroll
    for (int c = 0; c < 8; c++) {
      lA += g_lpar[c * BB * TT + b * TT + ia];
      lB += g_lpar[c * BB * TT + b * TT + ib];
    }
    const float lna = -__log2f(lA), lnb = -__log2f(lB);

    // stage Q through smem, hoist fragments to registers
#pragma unroll
    for (int e = 0; e < 4; e++) {
      int idx = t + e * 256, r = idx >> 3, c8 = idx & 7;   // idx < 1024
      size_t gb = ((size_t)(b * TT + i0 + r) * 64 + c8 * 8) * 2;
      cpa16(sb + (uint32_t)(r * 144 + c8 * 16), (const char*)g_qhi + gb);
    }
    CP_COMMIT(); CP_WAIT0();
    __syncthreads();
    const uint32_t arow = 16 * w + (lane & 15), aoff8 = (lane >> 4) * 8;
    uint32_t qa[4][4];
#pragma unroll
    for (int s = 0; s < 4; s++)
      ldsm4(qa[s], sb + arow * 144 + (s * 16 + aoff8) * 2);
    __syncthreads();   // all warps done with Q smem before KV overwrites

    const int npairs = ntiles >> 1;            // ntiles even (2 or 4)
    // first KV pair -> buf0 (@0)
    {
      const int j0 = jt0 * 64;
#pragma unroll
      for (int e = 0; e < 4; e++) {
        int idx = t + e * 256, r = idx >> 3, c8 = idx & 7;  // idx < 1024
        size_t gb = ((size_t)(b * TT + j0 + r) * 64 + c8 * 8) * 2;
        uint32_t off = (uint32_t)(r * 144 + c8 * 16);
        cpa16(sb + off,         (const char*)g_khi + gb);
        cpa16(sb + off + 18432, (const char*)g_vhi + gb);
      }
    }
    CP_COMMIT();

    const uint32_t brow = (lane & 7) + ((lane >> 4) & 1) * 8;
    const uint32_t boff8 = ((lane >> 3) & 1) * 8;
    const uint32_t vrow = (lane & 7) + ((lane >> 3) & 1) * 8;
    const uint32_t voff8 = ((lane >> 4) & 1) * 8;

    for (int it = 0; it < npairs; it++) {
      CP_WAIT0();
      __syncthreads();

      if (it + 1 < npairs) {
        const int jn = (jt0 + 2 * (it + 1)) * 64;
        const uint32_t nb = ((it + 1) & 1) * KVSZ;
#pragma unroll
        for (int e = 0; e < 4; e++) {
          int idx = t + e * 256, r = idx >> 3, c8 = idx & 7;
          size_t gb = ((size_t)(b * TT + jn + r) * 64 + c8 * 8) * 2;
          uint32_t off = nb + (uint32_t)(r * 144 + c8 * 16);
          cpa16(sb + off,         (const char*)g_khi + gb);
          cpa16(sb + off + 18432, (const char*)g_vhi + gb);
        }
      }
      CP_COMMIT();

      const uint32_t buf = (it & 1) * KVSZ;

#pragma unroll
      for (int half = 0; half < 2; half++) {
        const int j0 = (jt0 + 2 * it + half) * 64;
        const uint32_t KB = buf + half * 9216;
        const uint32_t VB = buf + 18432 + half * 9216;
        const bool full = (j0 + 64 <= i0);

#pragma unroll
        for (int p = 0; p < 4; p++) {
          float s0[4] = {}, s1[4] = {};
#pragma unroll
          for (int s = 0; s < 4; s++) {
            uint32_t bh[4];
            ldsm4(bh, sb + KB + (p * 16 + brow) * 144 + (s * 16 + boff8) * 2);
            mma16816h(s0, qa[s], bh[0], bh[1]);
            mma16816h(s1, qa[s], bh[2], bh[3]);
          }
          int j = j0 + p * 16 + tq * 2;      // nf = 2p
          float ca0 = fmaf((float)(j - ia), C2F, lna);
          float cb0 = fmaf((float)(j - ib), C2F, lnb);
          if (full) {
            s0[0] = exp2f(fmaf(s0[0], C2F, ca0));
            s0[1] = exp2f(fmaf(s0[1], C2F, ca0 + C2F));
            s0[2] = exp2f(fmaf(s0[2], C2F, cb0));
            s0[3] = exp2f(fmaf(s0[3], C2F, cb0 + C2F));
            s1[0] = exp2f(fmaf(s1[0], C2F, ca0 + 8.0f * C2F));
            s1[1] = exp2f(fmaf(s1[1], C2F, ca0 + 9.0f * C2F));
            s1[2] = exp2f(fmaf(s1[2], C2F, cb0 + 8.0f * C2F));
            s1[3] = exp2f(fmaf(s1[3], C2F, cb0 + 9.0f * C2F));
          } else {
            s0[0] = (j     <= ia) ? exp2f(fmaf(s0[0], C2F, ca0)) : 0.0f;
            s0[1] = (j + 1 <= ia) ? exp2f(fmaf(s0[1], C2F, ca0 + C2F)) : 0.0f;
            s0[2] = (j     <= ib) ? exp2f(fmaf(s0[2], C2F, cb0)) : 0.0f;
            s0[3] = (j + 1 <= ib) ? exp2f(fmaf(s0[3], C2F, cb0 + C2F)) : 0.0f;
            s1[0] = (j + 8 <= ia) ? exp2f(fmaf(s1[0], C2F, ca0 + 8.0f * C2F)) : 0.0f;
            s1[1] = (j + 9 <= ia) ? exp2f(fmaf(s1[1], C2F, ca0 + 9.0f * C2F)) : 0.0f;
            s1[2] = (j + 8 <= ib) ? exp2f(fmaf(s1[2], C2F, cb0 + 8.0f * C2F)) : 0.0f;
            s1[3] = (j + 9 <= ib) ? exp2f(fmaf(s1[3], C2F, cb0 + 9.0f * C2F)) : 0.0f;
          }
          stg2cs(att + (size_t)ia * TT + j,     s0[0], s0[1]);
          stg2cs(att + (size_t)ib * TT + j,     s0[2], s0[3]);
          stg2cs(att + (size_t)ia * TT + j + 8, s1[0], s1[1]);
          stg2cs(att + (size_t)ib * TT + j + 8, s1[2], s1[3]);

          // PV for this key group (s2 == p)
          uint32_t ah[4];
          ah[0] = packh(s0[0], s0[1]);
          ah[1] = packh(s0[2], s0[3]);
          ah[2] = packh(s1[0], s1[1]);
          ah[3] = packh(s1[2], s1[3]);
#pragma unroll
          for (int p2 = 0; p2 < 4; p2++) {
            uint32_t bh[4];
            ldsm4t(bh, sb + VB + (p * 16 + vrow) * 144 + (p2 * 16 + voff8) * 2);
            mma16816h(oa[2*p2],   ah, bh[0], bh[1]);
            mma16816h(oa[2*p2+1], ah, bh[2], bh[3]);
          }
        }
      }
    }

    float* opA = out + ((size_t)b * TT + ia) * HH;
    float* opB = out + ((size_t)b * TT + ib) * HH;
#pragma unroll
    for (int nf = 0; nf < 8; nf++) {
      int c = nf * 8 + tq * 2;
      atomicAdd(opA + c,     oa[nf][0]);
      atomicAdd(opA + c + 1, oa[nf][1]);
      atomicAdd(opB + c,     oa[nf][2]);
      atomicAdd(opB + c + 1, oa[nf][3]);
    }
  }

  // ---- zero-fill the strictly-upper part of this block's 256-col strip ----
  {
    const int jf0 = max(jt0, 2 * rt + 2);
    const int nf4 = (jt0 + 4 - jf0) * 16;
    if (nf4 > 0) {
      const float4 z = make_float4(0, 0, 0, 0);
      float4* a4 = (float4*)att;
      for (int r = w; r < 128; r += 8)
        for (int c = lane; c < nf4; c += 32)
          __stcs(&a4[(size_t)(i0 + r) * 512 + jf0 * 16 + c], z);
    }
  }
}

// ---------------------------------------------------------------------------
extern "C" void kernel_launch(void* const* d_in, const int* in_sizes, int n_in,
                              void* d_out, int out_size) {
  const float* x  = (const float*)d_in[0];
  const float* Wq = (const float*)d_in[1];
  const float* Wk = (const float*)d_in[2];
  const float* Wv = (const float*)d_in[3];
  float* out = (float*)d_out;

  k0<<<384, 256>>>(Wq, Wk, Wv);
  kz<<<1024, 256>>>(out);   // zero out-head (atomicAdd target)

  cudaFuncSetAttribute(qkv, cudaFuncAttributeMaxDynamicSharedMemorySize, 92160);
  qkv<<<128, 256, 92160>>>(x);

  cudaFuncSetAttribute(attnA, cudaFuncAttributeMaxDynamicSharedMemorySize, 18432);
  attnA<<<dim3(8, 128), 256, 18432>>>();

  cudaFuncSetAttribute(attnB, cudaFuncAttributeMaxDynamicSharedMemorySize, 73728);
  cudaFuncSetAttribute(attnB, cudaFuncAttributePreferredSharedMemoryCarveout,
                       cudaSharedmemCarveoutMaxShared);
  attnB<<<dim3(8, 128), 256, 73728>>>(out);
}